// round 4
// baseline (speedup 1.0000x reference)
#include <cuda_runtime.h>
#include <cstdint>

#define NV 50000
#define DD 64

// Scratch (static device arrays: allocation-free rule)
__device__ float g_h[(size_t)NV * DD];    // node projection h; reused as tmp after edge pass
__device__ float g_agg[(size_t)NV * DD];  // segment-sum accumulator

__device__ __forceinline__ uint32_t f2tf(float x) {
    uint32_t u;
    asm("cvt.rna.tf32.f32 %0, %1;" : "=r"(u) : "f"(x));
    return u;
}

__device__ __forceinline__ void mma8(float& d0, float& d1, float& d2, float& d3,
                                     uint32_t a0, uint32_t a1, uint32_t a2, uint32_t a3,
                                     uint32_t b0, uint32_t b1) {
    asm volatile(
        "mma.sync.aligned.m16n8k8.row.col.f32.tf32.tf32.f32 "
        "{%0,%1,%2,%3}, {%4,%5,%6,%7}, {%8,%9}, {%0,%1,%2,%3};"
        : "+f"(d0), "+f"(d1), "+f"(d2), "+f"(d3)
        : "r"(a0), "r"(a1), "r"(a2), "r"(a3), "r"(b0), "r"(b1));
}

// ShiftedSoftplus: softplus(x) - ln(2), numerically stable form
__device__ __forceinline__ float sspf(float x) {
    return fmaxf(x, 0.0f) + __logf(1.0f + __expf(-fabsf(x))) - 0.69314718055994531f;
}

// ---------------------------------------------------------------------------
// Single-layer GEMM: Y[M,64] = act?(X[M,64] @ W[64,64] + b)
// Block = 128 rows, 8 warps: warp = (mw 0..3 -> 32 rows, nw 0..1 -> 32 cols).
// Per warp: B-frags for its 32 cols cached in regs (reused over 2 row-subtiles).
// ---------------------------------------------------------------------------
template <bool ACT, bool ZERO_AGG>
__global__ __launch_bounds__(256)
void gemm64_kernel(const float* __restrict__ X, const float* __restrict__ W,
                   const float* __restrict__ bias, float* __restrict__ Y, int M)
{
    const int tid  = threadIdx.x;
    const int lane = tid & 31, warp = tid >> 5;
    const int mw = warp >> 1, nw = warp & 1;
    const int g = lane >> 2, tg = lane & 3;
    const int rb  = blockIdx.x * 128;
    const int ncb = nw * 32;

    if (ZERO_AGG) {
        float4* av = reinterpret_cast<float4*>(g_agg);
        #pragma unroll 4
        for (int i = tid; i < 128 * 16; i += 256) {
            int r = rb + (i >> 4);
            if (r < M) av[(size_t)r * 16 + (i & 15)] = make_float4(0.f, 0.f, 0.f, 0.f);
        }
    }

    // Preload B fragments: B tile (kstep k, ntile t): b0=W[8k+tg][n], b1=W[8k+tg+4][n], n=ncb+8t+g
    uint32_t bf[8][4][2];
    #pragma unroll
    for (int k = 0; k < 8; k++)
        #pragma unroll
        for (int t = 0; t < 4; t++) {
            int n = ncb + t * 8 + g;
            bf[k][t][0] = f2tf(W[(k * 8 + tg) * 64 + n]);
            bf[k][t][1] = f2tf(W[(k * 8 + tg + 4) * 64 + n]);
        }
    float2 bv[4];
    #pragma unroll
    for (int t = 0; t < 4; t++)
        bv[t] = *reinterpret_cast<const float2*>(&bias[ncb + t * 8 + 2 * tg]);

    #pragma unroll
    for (int s = 0; s < 2; s++) {
        const int r0   = rb + mw * 32 + s * 16;
        const int row0 = r0 + g, row1 = r0 + g + 8;
        float acc[4][4];
        #pragma unroll
        for (int t = 0; t < 4; t++) { acc[t][0] = acc[t][1] = acc[t][2] = acc[t][3] = 0.f; }

        #pragma unroll
        for (int k = 0; k < 8; k++) {
            const int c0 = k * 8 + tg, c1 = c0 + 4;
            float a0 = (row0 < M) ? X[(size_t)row0 * 64 + c0] : 0.f;
            float a1 = (row1 < M) ? X[(size_t)row1 * 64 + c0] : 0.f;
            float a2 = (row0 < M) ? X[(size_t)row0 * 64 + c1] : 0.f;
            float a3 = (row1 < M) ? X[(size_t)row1 * 64 + c1] : 0.f;
            uint32_t u0 = f2tf(a0), u1 = f2tf(a1), u2 = f2tf(a2), u3 = f2tf(a3);
            #pragma unroll
            for (int t = 0; t < 4; t++)
                mma8(acc[t][0], acc[t][1], acc[t][2], acc[t][3],
                     u0, u1, u2, u3, bf[k][t][0], bf[k][t][1]);
        }

        #pragma unroll
        for (int t = 0; t < 4; t++) {
            float v0 = acc[t][0] + bv[t].x, v1 = acc[t][1] + bv[t].y;
            float v2 = acc[t][2] + bv[t].x, v3 = acc[t][3] + bv[t].y;
            if (ACT) { v0 = sspf(v0); v1 = sspf(v1); v2 = sspf(v2); v3 = sspf(v3); }
            int col = ncb + t * 8 + 2 * tg;
            if (row0 < M) *reinterpret_cast<float2*>(&Y[(size_t)row0 * 64 + col]) = make_float2(v0, v1);
            if (row1 < M) *reinterpret_cast<float2*>(&Y[(size_t)row1 * 64 + col]) = make_float2(v2, v3);
        }
    }
}

// ---------------------------------------------------------------------------
// Fused edge kernel: f = ssp(ssp(EF@We1+b1)@We2+b2); msg = h[src]*f; red-add to agg[dst]
// Block = 128 edges. Layer1 -> smem C1 (stride 68 floats: conflict-free A reloads),
// sync, Layer2 from smem, epilogue does gather + red.global.add.v2.
// ---------------------------------------------------------------------------
__global__ __launch_bounds__(256)
void edge_kernel(const float* __restrict__ EF, const int* __restrict__ src,
                 const int* __restrict__ dst,
                 const float* __restrict__ W1, const float* __restrict__ b1,
                 const float* __restrict__ W2, const float* __restrict__ b2,
                 int E)
{
    __shared__ float C1[128 * 68];
    const int tid  = threadIdx.x;
    const int lane = tid & 31, warp = tid >> 5;
    const int mw = warp >> 1, nw = warp & 1;
    const int g = lane >> 2, tg = lane & 3;
    const int eb  = blockIdx.x * 128;
    const int ncb = nw * 32;

    // ---- Layer 1: B frags + bias ----
    uint32_t bf[8][4][2];
    #pragma unroll
    for (int k = 0; k < 8; k++)
        #pragma unroll
        for (int t = 0; t < 4; t++) {
            int n = ncb + t * 8 + g;
            bf[k][t][0] = f2tf(W1[(k * 8 + tg) * 64 + n]);
            bf[k][t][1] = f2tf(W1[(k * 8 + tg + 4) * 64 + n]);
        }
    float2 bv[4];
    #pragma unroll
    for (int t = 0; t < 4; t++)
        bv[t] = *reinterpret_cast<const float2*>(&b1[ncb + t * 8 + 2 * tg]);

    #pragma unroll
    for (int s = 0; s < 2; s++) {
        const int R0 = mw * 32 + s * 16;             // row within block
        const int e0 = eb + R0 + g, e1 = e0 + 8;     // global edge rows
        float acc[4][4];
        #pragma unroll
        for (int t = 0; t < 4; t++) { acc[t][0] = acc[t][1] = acc[t][2] = acc[t][3] = 0.f; }

        #pragma unroll
        for (int k = 0; k < 8; k++) {
            const int c0 = k * 8 + tg, c1 = c0 + 4;
            float a0 = (e0 < E) ? EF[(size_t)e0 * 64 + c0] : 0.f;
            float a1 = (e1 < E) ? EF[(size_t)e1 * 64 + c0] : 0.f;
            float a2 = (e0 < E) ? EF[(size_t)e0 * 64 + c1] : 0.f;
            float a3 = (e1 < E) ? EF[(size_t)e1 * 64 + c1] : 0.f;
            uint32_t u0 = f2tf(a0), u1 = f2tf(a1), u2 = f2tf(a2), u3 = f2tf(a3);
            #pragma unroll
            for (int t = 0; t < 4; t++)
                mma8(acc[t][0], acc[t][1], acc[t][2], acc[t][3],
                     u0, u1, u2, u3, bf[k][t][0], bf[k][t][1]);
        }

        #pragma unroll
        for (int t = 0; t < 4; t++) {
            float v0 = sspf(acc[t][0] + bv[t].x), v1 = sspf(acc[t][1] + bv[t].y);
            float v2 = sspf(acc[t][2] + bv[t].x), v3 = sspf(acc[t][3] + bv[t].y);
            int col = ncb + t * 8 + 2 * tg;
            *reinterpret_cast<float2*>(&C1[(R0 + g) * 68 + col])     = make_float2(v0, v1);
            *reinterpret_cast<float2*>(&C1[(R0 + g + 8) * 68 + col]) = make_float2(v2, v3);
        }
    }

    // ---- Layer 2: B frags + bias (overlap loads with the barrier) ----
    #pragma unroll
    for (int k = 0; k < 8; k++)
        #pragma unroll
        for (int t = 0; t < 4; t++) {
            int n = ncb + t * 8 + g;
            bf[k][t][0] = f2tf(W2[(k * 8 + tg) * 64 + n]);
            bf[k][t][1] = f2tf(W2[(k * 8 + tg + 4) * 64 + n]);
        }
    #pragma unroll
    for (int t = 0; t < 4; t++)
        bv[t] = *reinterpret_cast<const float2*>(&b2[ncb + t * 8 + 2 * tg]);

    __syncthreads();

    #pragma unroll
    for (int s = 0; s < 2; s++) {
        const int R0 = mw * 32 + s * 16;
        const int e0 = eb + R0 + g, e1 = e0 + 8;
        float acc[4][4];
        #pragma unroll
        for (int t = 0; t < 4; t++) { acc[t][0] = acc[t][1] = acc[t][2] = acc[t][3] = 0.f; }

        #pragma unroll
        for (int k = 0; k < 8; k++) {
            const int c0 = k * 8 + tg, c1 = c0 + 4;
            // stride 68 ≡ 4 (mod 32) banks: (4g + tg) hits all 32 banks -> conflict-free
            float a0 = C1[(R0 + g) * 68 + c0];
            float a1 = C1[(R0 + g + 8) * 68 + c0];
            float a2 = C1[(R0 + g) * 68 + c1];
            float a3 = C1[(R0 + g + 8) * 68 + c1];
            uint32_t u0 = f2tf(a0), u1 = f2tf(a1), u2 = f2tf(a2), u3 = f2tf(a3);
            #pragma unroll
            for (int t = 0; t < 4; t++)
                mma8(acc[t][0], acc[t][1], acc[t][2], acc[t][3],
                     u0, u1, u2, u3, bf[k][t][0], bf[k][t][1]);
        }

        // Epilogue: bias + ssp -> f; gather h[src]; vector red-add into agg[dst]
        const bool ok0 = (e0 < E), ok1 = (e1 < E);
        int s0 = 0, d0 = 0, s1 = 0, d1 = 0;
        if (ok0) { s0 = src[e0]; d0 = dst[e0]; }
        if (ok1) { s1 = src[e1]; d1 = dst[e1]; }

        #pragma unroll
        for (int t = 0; t < 4; t++) {
            int col = ncb + t * 8 + 2 * tg;
            float f0 = sspf(acc[t][0] + bv[t].x), f1 = sspf(acc[t][1] + bv[t].y);
            float f2 = sspf(acc[t][2] + bv[t].x), f3 = sspf(acc[t][3] + bv[t].y);
            if (ok0) {
                float2 hh = *reinterpret_cast<const float2*>(&g_h[(size_t)s0 * 64 + col]);
                float m0 = hh.x * f0, m1 = hh.y * f1;
                asm volatile("red.global.add.v2.f32 [%0], {%1, %2};"
                             :: "l"(&g_agg[(size_t)d0 * 64 + col]), "f"(m0), "f"(m1) : "memory");
            }
            if (ok1) {
                float2 hh = *reinterpret_cast<const float2*>(&g_h[(size_t)s1 * 64 + col]);
                float m0 = hh.x * f2, m1 = hh.y * f3;
                asm volatile("red.global.add.v2.f32 [%0], {%1, %2};"
                             :: "l"(&g_agg[(size_t)d1 * 64 + col]), "f"(m0), "f"(m1) : "memory");
            }
        }
    }
}

// ---------------------------------------------------------------------------
// Launch: h = node@Wn+bn (+zero agg) -> fused edge pass -> tmp = ssp(agg@Wc+bc)
//         -> out = tmp@Wo+bo.  All on the capture stream, no allocs, no syncs.
// ---------------------------------------------------------------------------
extern "C" void kernel_launch(void* const* d_in, const int* in_sizes, int n_in,
                              void* d_out, int out_size)
{
    const float* node = (const float*)d_in[0];
    const float* edge = (const float*)d_in[1];
    const int*   src  = (const int*)d_in[2];
    const int*   dst  = (const int*)d_in[3];
    const float* We1  = (const float*)d_in[4];
    const float* be1  = (const float*)d_in[5];
    const float* We2  = (const float*)d_in[6];
    const float* be2  = (const float*)d_in[7];
    const float* Wn   = (const float*)d_in[8];
    const float* bn   = (const float*)d_in[9];
    const float* Wc   = (const float*)d_in[10];
    const float* bc   = (const float*)d_in[11];
    const float* Wo   = (const float*)d_in[12];
    const float* bo   = (const float*)d_in[13];
    float* out = (float*)d_out;

    const int E  = in_sizes[2];
    const int Vn = in_sizes[0] / 64;

    float *h_ptr = nullptr, *agg_ptr = nullptr;
    cudaGetSymbolAddress((void**)&h_ptr, g_h);
    cudaGetSymbolAddress((void**)&agg_ptr, g_agg);

    const int nbV = (Vn + 127) / 128;
    const int nbE = (E + 127) / 128;

    // h = node @ Wn + bn ; zero agg
    gemm64_kernel<false, true><<<nbV, 256>>>(node, Wn, bn, h_ptr, Vn);
    // fused CFConv edge pass: agg += h[src] * ssp(ssp(edge@We1+b1)@We2+b2) scattered to dst
    edge_kernel<<<nbE, 256>>>(edge, src, dst, We1, be1, We2, be2, E);
    // tmp = ssp(agg @ Wc + bc)   (reuse g_h as tmp)
    gemm64_kernel<true, false><<<nbV, 256>>>(agg_ptr, Wc, bc, h_ptr, Vn);
    // out = tmp @ Wo + bo
    gemm64_kernel<false, false><<<nbV, 256>>>(h_ptr, Wo, bo, out, Vn);
}

// round 5
// speedup vs baseline: 1.3288x; 1.3288x over previous
#include <cuda_runtime.h>
#include <cstdint>

#define NV 50000
#define DD 64

// Scratch (static device arrays: allocation-free rule)
__device__ float g_h[(size_t)NV * DD];    // node projection h; reused as tmp after edge pass
__device__ float g_agg[(size_t)NV * DD];  // segment-sum accumulator

__device__ __forceinline__ uint32_t f2tf(float x) {
    uint32_t u;
    asm("cvt.rna.tf32.f32 %0, %1;" : "=r"(u) : "f"(x));
    return u;
}

__device__ __forceinline__ void mma8(float& d0, float& d1, float& d2, float& d3,
                                     uint32_t a0, uint32_t a1, uint32_t a2, uint32_t a3,
                                     uint32_t b0, uint32_t b1) {
    asm volatile(
        "mma.sync.aligned.m16n8k8.row.col.f32.tf32.tf32.f32 "
        "{%0,%1,%2,%3}, {%4,%5,%6,%7}, {%8,%9}, {%0,%1,%2,%3};"
        : "+f"(d0), "+f"(d1), "+f"(d2), "+f"(d3)
        : "r"(a0), "r"(a1), "r"(a2), "r"(a3), "r"(b0), "r"(b1));
}

// ShiftedSoftplus: softplus(x) - ln(2), numerically stable form
__device__ __forceinline__ float sspf(float x) {
    return fmaxf(x, 0.0f) + __logf(1.0f + __expf(-fabsf(x))) - 0.69314718055994531f;
}

// ---------------------------------------------------------------------------
// Exact-fp32 SIMT GEMM for the V-side projections:
//   Y[M,64] = act?(X[M,64] @ W[64,64] + b)
// Block = 64 rows, 256 threads. W and X tile staged in smem (pad 68 floats).
// Thread = (row r = tid>>2, col-quad q = tid&3 -> 16 cols). W reads are
// 4-way-distinct broadcasts (free), X reads conflict-free. FMA-bound.
// ---------------------------------------------------------------------------
template <bool ACT, bool ZERO_AGG>
__global__ __launch_bounds__(256)
void ngemm64_kernel(const float* __restrict__ X, const float* __restrict__ W,
                    const float* __restrict__ bias, float* __restrict__ Y, int M)
{
    __shared__ float Ws[64 * 68];
    __shared__ float Xs[64 * 68];
    const int tid = threadIdx.x;
    const int rb  = blockIdx.x * 64;

    if (ZERO_AGG) {
        float4* av = reinterpret_cast<float4*>(g_agg);
        #pragma unroll
        for (int p = 0; p < 4; p++) {
            int i = tid + 256 * p;                 // 64 rows * 16 f4
            int r = rb + (i >> 4);
            if (r < M) av[(size_t)r * 16 + (i & 15)] = make_float4(0.f, 0.f, 0.f, 0.f);
        }
    }

    // Stage W (64x64) and X tile (64 rows), coalesced float4.
    #pragma unroll
    for (int p = 0; p < 4; p++) {
        int i = tid + 256 * p;                     // 0..1023
        int row = i >> 4, q = i & 15;
        *reinterpret_cast<float4*>(&Ws[row * 68 + 4 * q]) =
            *reinterpret_cast<const float4*>(&W[row * 64 + 4 * q]);
        int r = rb + row;
        float4 xv = make_float4(0.f, 0.f, 0.f, 0.f);
        if (r < M) xv = *reinterpret_cast<const float4*>(&X[(size_t)r * 64 + 4 * q]);
        *reinterpret_cast<float4*>(&Xs[row * 68 + 4 * q]) = xv;
    }
    __syncthreads();

    const int r = tid >> 2, q = tid & 3;
    float acc[16];
    #pragma unroll
    for (int j = 0; j < 4; j++) {
        float4 bv = *reinterpret_cast<const float4*>(&bias[16 * q + 4 * j]);
        acc[4 * j + 0] = bv.x; acc[4 * j + 1] = bv.y;
        acc[4 * j + 2] = bv.z; acc[4 * j + 3] = bv.w;
    }

    #pragma unroll 8
    for (int k = 0; k < 64; k++) {
        float a = Xs[r * 68 + k];
        const float4* wrow = reinterpret_cast<const float4*>(&Ws[k * 68 + 16 * q]);
        float4 w0 = wrow[0], w1 = wrow[1], w2 = wrow[2], w3 = wrow[3];
        acc[0]  = fmaf(a, w0.x, acc[0]);  acc[1]  = fmaf(a, w0.y, acc[1]);
        acc[2]  = fmaf(a, w0.z, acc[2]);  acc[3]  = fmaf(a, w0.w, acc[3]);
        acc[4]  = fmaf(a, w1.x, acc[4]);  acc[5]  = fmaf(a, w1.y, acc[5]);
        acc[6]  = fmaf(a, w1.z, acc[6]);  acc[7]  = fmaf(a, w1.w, acc[7]);
        acc[8]  = fmaf(a, w2.x, acc[8]);  acc[9]  = fmaf(a, w2.y, acc[9]);
        acc[10] = fmaf(a, w2.z, acc[10]); acc[11] = fmaf(a, w2.w, acc[11]);
        acc[12] = fmaf(a, w3.x, acc[12]); acc[13] = fmaf(a, w3.y, acc[13]);
        acc[14] = fmaf(a, w3.z, acc[14]); acc[15] = fmaf(a, w3.w, acc[15]);
    }

    const int row = rb + r;
    if (row < M) {
        if (ACT) {
            #pragma unroll
            for (int j = 0; j < 16; j++) acc[j] = sspf(acc[j]);
        }
        float4* yp = reinterpret_cast<float4*>(&Y[(size_t)row * 64 + 16 * q]);
        #pragma unroll
        for (int j = 0; j < 4; j++)
            yp[j] = make_float4(acc[4 * j], acc[4 * j + 1], acc[4 * j + 2], acc[4 * j + 3]);
    }
}

// ---------------------------------------------------------------------------
// Fused edge kernel (tf32 mma):
//   f = ssp(ssp(EF@We1+b1)@We2+b2); msg = h[src]*f; red-add into agg[dst].
// Block = 128 edges, 8 warps (mw 0..3 x nw 0..1). One padded smem tile SB
// is reused: EF stage -> layer1 reads -> C1 -> layer2 reads -> f stage ->
// transposed epilogue with coalesced red.global.add.v4.f32.
// ---------------------------------------------------------------------------
__global__ __launch_bounds__(256)
void edge_kernel(const float* __restrict__ EF, const int* __restrict__ src,
                 const int* __restrict__ dst,
                 const float* __restrict__ W1, const float* __restrict__ b1,
                 const float* __restrict__ W2, const float* __restrict__ b2,
                 int E)
{
    __shared__ float SB[128 * 68];
    const int tid  = threadIdx.x;
    const int lane = tid & 31, warp = tid >> 5;
    const int mw = warp >> 1, nw = warp & 1;
    const int g = lane >> 2, tg = lane & 3;
    const int eb  = blockIdx.x * 128;
    const int ncb = nw * 32;

    // ---- Stage EF tile (coalesced float4) ----
    #pragma unroll
    for (int p = 0; p < 8; p++) {
        int i = tid + 256 * p;                     // 0..2047 = 128 rows * 16 f4
        int row = i >> 4, q = i & 15;
        int e = eb + row;
        float4 v = make_float4(0.f, 0.f, 0.f, 0.f);
        if (e < E) v = *reinterpret_cast<const float4*>(&EF[(size_t)e * 64 + 4 * q]);
        *reinterpret_cast<float4*>(&SB[row * 68 + 4 * q]) = v;
    }

    // ---- Layer-1 B fragments ----
    uint32_t bf[8][4][2];
    #pragma unroll
    for (int k = 0; k < 8; k++)
        #pragma unroll
        for (int t = 0; t < 4; t++) {
            int n = ncb + t * 8 + g;
            bf[k][t][0] = f2tf(W1[(k * 8 + tg) * 64 + n]);
            bf[k][t][1] = f2tf(W1[(k * 8 + tg + 4) * 64 + n]);
        }
    float2 bv[4];
    #pragma unroll
    for (int t = 0; t < 4; t++)
        bv[t] = *reinterpret_cast<const float2*>(&b1[ncb + t * 8 + 2 * tg]);

    __syncthreads();

    // ---- Layer 1 compute (A from smem; pad 68 -> bank (4g+tg): conflict-free) ----
    float acc[2][4][4];
    #pragma unroll
    for (int s = 0; s < 2; s++) {
        const int R0 = mw * 32 + s * 16;
        #pragma unroll
        for (int t = 0; t < 4; t++)
            acc[s][t][0] = acc[s][t][1] = acc[s][t][2] = acc[s][t][3] = 0.f;
        #pragma unroll
        for (int k = 0; k < 8; k++) {
            const int c0 = k * 8 + tg, c1 = c0 + 4;
            uint32_t u0 = f2tf(SB[(R0 + g) * 68 + c0]);
            uint32_t u1 = f2tf(SB[(R0 + g + 8) * 68 + c0]);
            uint32_t u2 = f2tf(SB[(R0 + g) * 68 + c1]);
            uint32_t u3 = f2tf(SB[(R0 + g + 8) * 68 + c1]);
            #pragma unroll
            for (int t = 0; t < 4; t++)
                mma8(acc[s][t][0], acc[s][t][1], acc[s][t][2], acc[s][t][3],
                     u0, u1, u2, u3, bf[k][t][0], bf[k][t][1]);
        }
    }
    __syncthreads();   // all layer-1 reads of SB done

    // ---- Write C1 = ssp(acc + b1) into SB ----
    #pragma unroll
    for (int s = 0; s < 2; s++) {
        const int R0 = mw * 32 + s * 16;
        #pragma unroll
        for (int t = 0; t < 4; t++) {
            int col = ncb + t * 8 + 2 * tg;
            float v0 = sspf(acc[s][t][0] + bv[t].x), v1 = sspf(acc[s][t][1] + bv[t].y);
            float v2 = sspf(acc[s][t][2] + bv[t].x), v3 = sspf(acc[s][t][3] + bv[t].y);
            *reinterpret_cast<float2*>(&SB[(R0 + g) * 68 + col])     = make_float2(v0, v1);
            *reinterpret_cast<float2*>(&SB[(R0 + g + 8) * 68 + col]) = make_float2(v2, v3);
        }
    }

    // ---- Layer-2 B fragments (overlap with barrier) ----
    #pragma unroll
    for (int k = 0; k < 8; k++)
        #pragma unroll
        for (int t = 0; t < 4; t++) {
            int n = ncb + t * 8 + g;
            bf[k][t][0] = f2tf(W2[(k * 8 + tg) * 64 + n]);
            bf[k][t][1] = f2tf(W2[(k * 8 + tg + 4) * 64 + n]);
        }
    #pragma unroll
    for (int t = 0; t < 4; t++)
        bv[t] = *reinterpret_cast<const float2*>(&b2[ncb + t * 8 + 2 * tg]);

    __syncthreads();   // C1 fully written

    // ---- Layer 2 compute ----
    #pragma unroll
    for (int s = 0; s < 2; s++) {
        const int R0 = mw * 32 + s * 16;
        #pragma unroll
        for (int t = 0; t < 4; t++)
            acc[s][t][0] = acc[s][t][1] = acc[s][t][2] = acc[s][t][3] = 0.f;
        #pragma unroll
        for (int k = 0; k < 8; k++) {
            const int c0 = k * 8 + tg, c1 = c0 + 4;
            uint32_t u0 = f2tf(SB[(R0 + g) * 68 + c0]);
            uint32_t u1 = f2tf(SB[(R0 + g + 8) * 68 + c0]);
            uint32_t u2 = f2tf(SB[(R0 + g) * 68 + c1]);
            uint32_t u3 = f2tf(SB[(R0 + g + 8) * 68 + c1]);
            #pragma unroll
            for (int t = 0; t < 4; t++)
                mma8(acc[s][t][0], acc[s][t][1], acc[s][t][2], acc[s][t][3],
                     u0, u1, u2, u3, bf[k][t][0], bf[k][t][1]);
        }
    }
    __syncthreads();   // all layer-2 reads of SB done

    // ---- Stage f = ssp(acc + b2) into SB ----
    #pragma unroll
    for (int s = 0; s < 2; s++) {
        const int R0 = mw * 32 + s * 16;
        #pragma unroll
        for (int t = 0; t < 4; t++) {
            int col = ncb + t * 8 + 2 * tg;
            float v0 = sspf(acc[s][t][0] + bv[t].x), v1 = sspf(acc[s][t][1] + bv[t].y);
            float v2 = sspf(acc[s][t][2] + bv[t].x), v3 = sspf(acc[s][t][3] + bv[t].y);
            *reinterpret_cast<float2*>(&SB[(R0 + g) * 68 + col])     = make_float2(v0, v1);
            *reinterpret_cast<float2*>(&SB[(R0 + g + 8) * 68 + col]) = make_float2(v2, v3);
        }
    }
    __syncthreads();   // f fully staged

    // ---- Transposed epilogue: gather h[src], multiply, vector-red to agg[dst] ----
    {
        const int row = tid >> 1;                  // 0..127, fixed per thread
        const int e = eb + row;
        if (e < E) {
            const int sN = src[e], dN = dst[e];
            const float4* hp = reinterpret_cast<const float4*>(&g_h[(size_t)sN * 64]);
            float*        ap = &g_agg[(size_t)dN * 64];
            #pragma unroll
            for (int j = 0; j < 8; j++) {
                int f4i = (tid & 1) + 2 * j;
                float4 f = *reinterpret_cast<const float4*>(&SB[row * 68 + 4 * f4i]);
                float4 h4 = __ldg(&hp[f4i]);
                float m0 = f.x * h4.x, m1 = f.y * h4.y, m2 = f.z * h4.z, m3 = f.w * h4.w;
                asm volatile("red.global.add.v4.f32 [%0], {%1, %2, %3, %4};"
                             :: "l"(ap + 4 * f4i), "f"(m0), "f"(m1), "f"(m2), "f"(m3)
                             : "memory");
            }
        }
    }
}

// ---------------------------------------------------------------------------
// Launch: h = node@Wn+bn (+zero agg) -> fused edge pass -> tmp = ssp(agg@Wc+bc)
//         -> out = tmp@Wo+bo.  All on the capture stream, no allocs, no syncs.
// ---------------------------------------------------------------------------
extern "C" void kernel_launch(void* const* d_in, const int* in_sizes, int n_in,
                              void* d_out, int out_size)
{
    const float* node = (const float*)d_in[0];
    const float* edge = (const float*)d_in[1];
    const int*   src  = (const int*)d_in[2];
    const int*   dst  = (const int*)d_in[3];
    const float* We1  = (const float*)d_in[4];
    const float* be1  = (const float*)d_in[5];
    const float* We2  = (const float*)d_in[6];
    const float* be2  = (const float*)d_in[7];
    const float* Wn   = (const float*)d_in[8];
    const float* bn   = (const float*)d_in[9];
    const float* Wc   = (const float*)d_in[10];
    const float* bc   = (const float*)d_in[11];
    const float* Wo   = (const float*)d_in[12];
    const float* bo   = (const float*)d_in[13];
    float* out = (float*)d_out;

    const int E  = in_sizes[2];
    const int Vn = in_sizes[0] / 64;

    float *h_ptr = nullptr, *agg_ptr = nullptr;
    cudaGetSymbolAddress((void**)&h_ptr, g_h);
    cudaGetSymbolAddress((void**)&agg_ptr, g_agg);

    const int nbV = (Vn + 63) / 64;
    const int nbE = (E + 127) / 128;

    // h = node @ Wn + bn ; zero agg   (exact fp32)
    ngemm64_kernel<false, true><<<nbV, 256>>>(node, Wn, bn, h_ptr, Vn);
    // fused CFConv edge pass (tf32 mma): agg += h[src] * ssp(ssp(edge@W1+b1)@W2+b2)
    edge_kernel<<<nbE, 256>>>(edge, src, dst, We1, be1, We2, be2, E);
    // tmp = ssp(agg @ Wc + bc)   (reuse g_h as tmp, exact fp32)
    ngemm64_kernel<true, false><<<nbV, 256>>>(agg_ptr, Wc, bc, h_ptr, Vn);
    // out = tmp @ Wo + bo        (exact fp32)
    ngemm64_kernel<false, false><<<nbV, 256>>>(h_ptr, Wo, bo, out, Vn);
}

// round 8
// speedup vs baseline: 2.0621x; 1.5519x over previous
#include <cuda_runtime.h>
#include <cstdint>

#define NV 50000
#define DD 64

// Scratch (static device arrays: allocation-free rule)
__device__ float g_h[(size_t)NV * DD];    // node projection h; reused as tmp after edge pass
__device__ float g_agg[(size_t)NV * DD];  // segment-sum accumulator

__device__ __forceinline__ uint32_t f2tf(float x) {
    uint32_t u;
    asm("cvt.rna.tf32.f32 %0, %1;" : "=r"(u) : "f"(x));
    return u;
}

__device__ __forceinline__ void mma8(float& d0, float& d1, float& d2, float& d3,
                                     uint32_t a0, uint32_t a1, uint32_t a2, uint32_t a3,
                                     uint32_t b0, uint32_t b1) {
    asm volatile(
        "mma.sync.aligned.m16n8k8.row.col.f32.tf32.tf32.f32 "
        "{%0,%1,%2,%3}, {%4,%5,%6,%7}, {%8,%9}, {%0,%1,%2,%3};"
        : "+f"(d0), "+f"(d1), "+f"(d2), "+f"(d3)
        : "r"(a0), "r"(a1), "r"(a2), "r"(a3), "r"(b0), "r"(b1));
}

// ShiftedSoftplus: softplus(x) - ln(2), numerically stable
__device__ __forceinline__ float sspf(float x) {
    return fmaxf(x, 0.0f) + __logf(1.0f + __expf(-fabsf(x))) - 0.69314718055994531f;
}

// Shared-memory budget (both kernels): 32KB W-fragments + 8 warps * 16 rows * 68 floats
#define SMEM_BYTES (32768 + 8 * 16 * 68 * 4)

// ---------------------------------------------------------------------------
// Split-tf32 GEMM: Y[M,64] = act?(X[M,64] @ W[64,64] + b), fp32-accurate.
// Block = 8 warps * 16 rows. W staged once as hi/lo tf32 fragments in smem;
// each warp computes its 16 rows x 64 cols independently (A via padded smem).
// acc += a_hi*B_hi + a_lo*B_hi + a_hi*B_lo   (error ~2^-21)
// ---------------------------------------------------------------------------
template <bool ACT, bool ZERO_AGG>
__global__ __launch_bounds__(256, 3)
void sgemm64_kernel(const float* __restrict__ X, const float* __restrict__ W,
                    const float* __restrict__ bias, float* __restrict__ Y, int M)
{
    extern __shared__ uint32_t SM[];
    uint32_t* Wf = SM;                         // 2048 tuples * {hi0,hi1,lo0,lo1}
    float*    Ab = (float*)(SM + 8192);        // 8 * 16 * 68

    const int tid = threadIdx.x, lane = tid & 31, warp = tid >> 5;
    const int g = lane >> 2, tg = lane & 3;
    const int rb = blockIdx.x * 128;

    if (ZERO_AGG) {
        float4* av = reinterpret_cast<float4*>(g_agg);
        #pragma unroll
        for (int p = 0; p < 8; p++) {
            int i = tid + 256 * p;             // 128 rows * 16 f4
            int r = rb + (i >> 4);
            if (r < M) av[(size_t)r * 16 + (i & 15)] = make_float4(0.f, 0.f, 0.f, 0.f);
        }
    }

    // Stage W as hi/lo tf32 fragments: tuple i = (k*8+t)*32 + lane
    #pragma unroll
    for (int p = 0; p < 8; p++) {
        int i = tid + 256 * p;                 // 0..2047
        int l = i & 31, t = (i >> 5) & 7, k = i >> 8;
        int gg = l >> 2, tt = l & 3;
        int col = 8 * t + gg;
        float w0 = W[(8 * k + tt) * 64 + col];
        float w1 = W[(8 * k + tt + 4) * 64 + col];
        uint32_t h0 = f2tf(w0), h1 = f2tf(w1);
        uint32_t l0 = f2tf(w0 - __uint_as_float(h0));
        uint32_t l1 = f2tf(w1 - __uint_as_float(h1));
        reinterpret_cast<uint4*>(Wf)[i] = make_uint4(h0, h1, l0, l1);
    }
    __syncthreads();

    float* A = Ab + warp * 16 * 68;
    const int r0 = rb + warp * 16;

    // Stage X rows (coalesced f4; pad 68 -> conflict-free scalar reads)
    #pragma unroll
    for (int p = 0; p < 8; p++) {
        int idx = p * 32 + lane;               // 16 rows * 16 f4
        int r = idx >> 4, q = idx & 15;
        int row = r0 + r;
        float4 v = make_float4(0.f, 0.f, 0.f, 0.f);
        if (row < M) v = *reinterpret_cast<const float4*>(&X[(size_t)row * 64 + 4 * q]);
        *reinterpret_cast<float4*>(&A[r * 68 + 4 * q]) = v;
    }
    __syncwarp();

    float acc[8][4];
    #pragma unroll
    for (int t = 0; t < 8; t++) { acc[t][0] = acc[t][1] = acc[t][2] = acc[t][3] = 0.f; }

    #pragma unroll
    for (int k = 0; k < 8; k++) {
        const int c0 = 8 * k + tg;
        float a0 = A[g * 68 + c0],       a1 = A[(g + 8) * 68 + c0];
        float a2 = A[g * 68 + c0 + 4],   a3 = A[(g + 8) * 68 + c0 + 4];
        uint32_t h0 = f2tf(a0), h1 = f2tf(a1), h2 = f2tf(a2), h3 = f2tf(a3);
        uint32_t o0 = f2tf(a0 - __uint_as_float(h0));
        uint32_t o1 = f2tf(a1 - __uint_as_float(h1));
        uint32_t o2 = f2tf(a2 - __uint_as_float(h2));
        uint32_t o3 = f2tf(a3 - __uint_as_float(h3));
        #pragma unroll
        for (int t = 0; t < 8; t++) {
            uint4 bb = reinterpret_cast<const uint4*>(Wf)[(k * 8 + t) * 32 + lane];
            mma8(acc[t][0], acc[t][1], acc[t][2], acc[t][3], h0, h1, h2, h3, bb.x, bb.y);
            mma8(acc[t][0], acc[t][1], acc[t][2], acc[t][3], o0, o1, o2, o3, bb.x, bb.y);
            mma8(acc[t][0], acc[t][1], acc[t][2], acc[t][3], h0, h1, h2, h3, bb.z, bb.w);
        }
    }

    const int row0 = r0 + g, row1 = r0 + g + 8;
    #pragma unroll
    for (int t = 0; t < 8; t++) {
        float2 bv = *reinterpret_cast<const float2*>(&bias[8 * t + 2 * tg]);
        float v0 = acc[t][0] + bv.x, v1 = acc[t][1] + bv.y;
        float v2 = acc[t][2] + bv.x, v3 = acc[t][3] + bv.y;
        if (ACT) { v0 = sspf(v0); v1 = sspf(v1); v2 = sspf(v2); v3 = sspf(v3); }
        int col = 8 * t + 2 * tg;
        if (row0 < M) *reinterpret_cast<float2*>(&Y[(size_t)row0 * 64 + col]) = make_float2(v0, v1);
        if (row1 < M) *reinterpret_cast<float2*>(&Y[(size_t)row1 * 64 + col]) = make_float2(v2, v3);
    }
}

// ---------------------------------------------------------------------------
// Fused edge kernel, warp-independent:
//   f = ssp(ssp(EF@W1+b1)@W2+b2); agg[dst] += h[src]*f  (red.global.add.v4)
// One cooperative W1/W2 tf32-fragment staging + __syncthreads, then each warp
// owns 16 edges end-to-end through its private padded smem tile (syncwarp only).
// ---------------------------------------------------------------------------
__global__ __launch_bounds__(256, 3)
void edge_kernel(const float* __restrict__ EF, const int* __restrict__ src,
                 const int* __restrict__ dst,
                 const float* __restrict__ W1, const float* __restrict__ b1,
                 const float* __restrict__ W2, const float* __restrict__ b2,
                 int E)
{
    extern __shared__ uint32_t SM[];
    uint32_t* Wf1 = SM;                        // 4096 u32
    uint32_t* Wf2 = SM + 4096;                 // 4096 u32
    float*    Ab  = (float*)(SM + 8192);       // 8 * 16 * 68

    const int tid = threadIdx.x, lane = tid & 31, warp = tid >> 5;
    const int g = lane >> 2, tg = lane & 3;

    // Stage W1/W2 tf32 fragments: tuple i = (k*8+t)*32 + lane -> {b0,b1}
    #pragma unroll
    for (int p = 0; p < 8; p++) {
        int i = tid + 256 * p;                 // 0..2047
        int l = i & 31, t = (i >> 5) & 7, k = i >> 8;
        int gg = l >> 2, tt = l & 3;
        int col = 8 * t + gg;
        Wf1[2 * i]     = f2tf(W1[(8 * k + tt) * 64 + col]);
        Wf1[2 * i + 1] = f2tf(W1[(8 * k + tt + 4) * 64 + col]);
        Wf2[2 * i]     = f2tf(W2[(8 * k + tt) * 64 + col]);
        Wf2[2 * i + 1] = f2tf(W2[(8 * k + tt + 4) * 64 + col]);
    }
    __syncthreads();

    float* A = Ab + warp * 16 * 68;
    const int e0 = blockIdx.x * 128 + warp * 16;

    // Stage 16 edge-feature rows (coalesced f4)
    #pragma unroll
    for (int p = 0; p < 8; p++) {
        int idx = p * 32 + lane;
        int r = idx >> 4, q = idx & 15;
        int e = e0 + r;
        float4 v = make_float4(0.f, 0.f, 0.f, 0.f);
        if (e < E) v = *reinterpret_cast<const float4*>(&EF[(size_t)e * 64 + 4 * q]);
        *reinterpret_cast<float4*>(&A[r * 68 + 4 * q]) = v;
    }
    __syncwarp();

    float acc[8][4];

    // ---- Layer 1 ----
    #pragma unroll
    for (int t = 0; t < 8; t++) { acc[t][0] = acc[t][1] = acc[t][2] = acc[t][3] = 0.f; }
    #pragma unroll
    for (int k = 0; k < 8; k++) {
        const int c0 = 8 * k + tg;
        uint32_t u0 = f2tf(A[g * 68 + c0]);
        uint32_t u1 = f2tf(A[(g + 8) * 68 + c0]);
        uint32_t u2 = f2tf(A[g * 68 + c0 + 4]);
        uint32_t u3 = f2tf(A[(g + 8) * 68 + c0 + 4]);
        #pragma unroll
        for (int t = 0; t < 8; t++) {
            uint2 bb = *reinterpret_cast<const uint2*>(&Wf1[((k * 8 + t) * 32 + lane) * 2]);
            mma8(acc[t][0], acc[t][1], acc[t][2], acc[t][3], u0, u1, u2, u3, bb.x, bb.y);
        }
    }
    __syncwarp();   // all layer-1 reads of A done before overwrite

    // C1 = ssp(acc + b1) -> A
    #pragma unroll
    for (int t = 0; t < 8; t++) {
        float2 bv = *reinterpret_cast<const float2*>(&b1[8 * t + 2 * tg]);
        int col = 8 * t + 2 * tg;
        *reinterpret_cast<float2*>(&A[g * 68 + col]) =
            make_float2(sspf(acc[t][0] + bv.x), sspf(acc[t][1] + bv.y));
        *reinterpret_cast<float2*>(&A[(g + 8) * 68 + col]) =
            make_float2(sspf(acc[t][2] + bv.x), sspf(acc[t][3] + bv.y));
    }
    __syncwarp();

    // ---- Layer 2 ----
    #pragma unroll
    for (int t = 0; t < 8; t++) { acc[t][0] = acc[t][1] = acc[t][2] = acc[t][3] = 0.f; }
    #pragma unroll
    for (int k = 0; k < 8; k++) {
        const int c0 = 8 * k + tg;
        uint32_t u0 = f2tf(A[g * 68 + c0]);
        uint32_t u1 = f2tf(A[(g + 8) * 68 + c0]);
        uint32_t u2 = f2tf(A[g * 68 + c0 + 4]);
        uint32_t u3 = f2tf(A[(g + 8) * 68 + c0 + 4]);
        #pragma unroll
        for (int t = 0; t < 8; t++) {
            uint2 bb = *reinterpret_cast<const uint2*>(&Wf2[((k * 8 + t) * 32 + lane) * 2]);
            mma8(acc[t][0], acc[t][1], acc[t][2], acc[t][3], u0, u1, u2, u3, bb.x, bb.y);
        }
    }
    __syncwarp();

    // f = ssp(acc + b2) -> A
    #pragma unroll
    for (int t = 0; t < 8; t++) {
        float2 bv = *reinterpret_cast<const float2*>(&b2[8 * t + 2 * tg]);
        int col = 8 * t + 2 * tg;
        *reinterpret_cast<float2*>(&A[g * 68 + col]) =
            make_float2(sspf(acc[t][0] + bv.x), sspf(acc[t][1] + bv.y));
        *reinterpret_cast<float2*>(&A[(g + 8) * 68 + col]) =
            make_float2(sspf(acc[t][2] + bv.x), sspf(acc[t][3] + bv.y));
    }
    __syncwarp();

    // Epilogue: 2 lanes per edge; gather h[src] f4, multiply, red.v4 to agg[dst]
    {
        const int r = lane >> 1, half = lane & 1;
        const int e = e0 + r;
        if (e < E) {
            const int sN = src[e], dN = dst[e];
            const float4* hp = reinterpret_cast<const float4*>(&g_h[(size_t)sN * 64]);
            float*        ap = &g_agg[(size_t)dN * 64];
            #pragma unroll
            for (int j = 0; j < 8; j++) {
                int f4i = half + 2 * j;
                float4 f  = *reinterpret_cast<const float4*>(&A[r * 68 + 4 * f4i]);
                float4 h4 = __ldg(&hp[f4i]);
                float m0 = f.x * h4.x, m1 = f.y * h4.y, m2 = f.z * h4.z, m3 = f.w * h4.w;
                asm volatile("red.global.add.v4.f32 [%0], {%1, %2, %3, %4};"
                             :: "l"(ap + 4 * f4i), "f"(m0), "f"(m1), "f"(m2), "f"(m3)
                             : "memory");
            }
        }
    }
}

// ---------------------------------------------------------------------------
// Launch sequence (one stream, graph-capturable, no allocs/syncs)
// ---------------------------------------------------------------------------
extern "C" void kernel_launch(void* const* d_in, const int* in_sizes, int n_in,
                              void* d_out, int out_size)
{
    const float* node = (const float*)d_in[0];
    const float* edge = (const float*)d_in[1];
    const int*   src  = (const int*)d_in[2];
    const int*   dst  = (const int*)d_in[3];
    const float* We1  = (const float*)d_in[4];
    const float* be1  = (const float*)d_in[5];
    const float* We2  = (const float*)d_in[6];
    const float* be2  = (const float*)d_in[7];
    const float* Wn   = (const float*)d_in[8];
    const float* bn   = (const float*)d_in[9];
    const float* Wc   = (const float*)d_in[10];
    const float* bc   = (const float*)d_in[11];
    const float* Wo   = (const float*)d_in[12];
    const float* bo   = (const float*)d_in[13];
    float* out = (float*)d_out;

    const int E  = in_sizes[2];
    const int Vn = in_sizes[0] / 64;

    float *h_ptr = nullptr, *agg_ptr = nullptr;
    cudaGetSymbolAddress((void**)&h_ptr, g_h);
    cudaGetSymbolAddress((void**)&agg_ptr, g_agg);

    cudaFuncSetAttribute(sgemm64_kernel<false, true>,
                         cudaFuncAttributeMaxDynamicSharedMemorySize, SMEM_BYTES);
    cudaFuncSetAttribute(sgemm64_kernel<true, false>,
                         cudaFuncAttributeMaxDynamicSharedMemorySize, SMEM_BYTES);
    cudaFuncSetAttribute(sgemm64_kernel<false, false>,
                         cudaFuncAttributeMaxDynamicSharedMemorySize, SMEM_BYTES);
    cudaFuncSetAttribute(edge_kernel,
                         cudaFuncAttributeMaxDynamicSharedMemorySize, SMEM_BYTES);

    const int nbV = (Vn + 127) / 128;
    const int nbE = (E + 127) / 128;

    // h = node @ Wn + bn ; zero agg   (split-tf32, fp32-accurate)
    sgemm64_kernel<false, true><<<nbV, 256, SMEM_BYTES>>>(node, Wn, bn, h_ptr, Vn);
    // fused CFConv edge pass: agg += h[src] * ssp(ssp(edge@W1+b1)@W2+b2)
    edge_kernel<<<nbE, 256, SMEM_BYTES>>>(edge, src, dst, We1, be1, We2, be2, E);
    // tmp = ssp(agg @ Wc + bc)   (reuse g_h)
    sgemm64_kernel<true, false><<<nbV, 256, SMEM_BYTES>>>(agg_ptr, Wc, bc, h_ptr, Vn);
    // out = tmp @ Wo + bo
    sgemm64_kernel<false, false><<<nbV, 256, SMEM_BYTES>>>(h_ptr, Wo, bo, out, Vn);
}

// round 9
// speedup vs baseline: 2.2349x; 1.0838x over previous
#include <cuda_runtime.h>
#include <cstdint>

#define NV 50000
#define DD 64

// Scratch (static device arrays: allocation-free rule)
__device__ float g_h[(size_t)NV * DD];    // node projection h
__device__ float g_agg[(size_t)NV * DD];  // segment-sum accumulator

__device__ __forceinline__ uint32_t f2tf(float x) {
    uint32_t u;
    asm("cvt.rna.tf32.f32 %0, %1;" : "=r"(u) : "f"(x));
    return u;
}

__device__ __forceinline__ void mma8(float& d0, float& d1, float& d2, float& d3,
                                     uint32_t a0, uint32_t a1, uint32_t a2, uint32_t a3,
                                     uint32_t b0, uint32_t b1) {
    asm volatile(
        "mma.sync.aligned.m16n8k8.row.col.f32.tf32.tf32.f32 "
        "{%0,%1,%2,%3}, {%4,%5,%6,%7}, {%8,%9}, {%0,%1,%2,%3};"
        : "+f"(d0), "+f"(d1), "+f"(d2), "+f"(d3)
        : "r"(a0), "r"(a1), "r"(a2), "r"(a3), "r"(b0), "r"(b1));
}

// ShiftedSoftplus: softplus(x) - ln(2), numerically stable
__device__ __forceinline__ float sspf(float x) {
    return fmaxf(x, 0.0f) + __logf(1.0f + __expf(-fabsf(x))) - 0.69314718055994531f;
}

// Smem budgets
#define SMEM_GEMM  (32768 + 8 * 16 * 68 * 4)              // 50176
#define SMEM_EDGE  (32768 + 8 * 32 * 68 * 4)              // 102400
#define SMEM_CF    (65536 + 8 * 16 * 68 * 4)              // 82944

// ---------------------------------------------------------------------------
// Split-tf32 GEMM (fp32-accurate): Y[M,64] = X[M,64] @ W[64,64] + b
// Used for the node projection h (and zeroing agg).
// ---------------------------------------------------------------------------
template <bool ZERO_AGG>
__global__ __launch_bounds__(256, 3)
void sgemm64_kernel(const float* __restrict__ X, const float* __restrict__ W,
                    const float* __restrict__ bias, float* __restrict__ Y, int M)
{
    extern __shared__ uint32_t SM[];
    uint32_t* Wf = SM;                         // 2048 tuples {hi0,hi1,lo0,lo1}
    float*    Ab = (float*)(SM + 8192);

    const int tid = threadIdx.x, lane = tid & 31, warp = tid >> 5;
    const int g = lane >> 2, tg = lane & 3;
    const int rb = blockIdx.x * 128;

    if (ZERO_AGG) {
        float4* av = reinterpret_cast<float4*>(g_agg);
        #pragma unroll
        for (int p = 0; p < 8; p++) {
            int i = tid + 256 * p;
            int r = rb + (i >> 4);
            if (r < M) av[(size_t)r * 16 + (i & 15)] = make_float4(0.f, 0.f, 0.f, 0.f);
        }
    }

    #pragma unroll
    for (int p = 0; p < 8; p++) {
        int i = tid + 256 * p;                 // 0..2047
        int l = i & 31, t = (i >> 5) & 7, k = i >> 8;
        int gg = l >> 2, tt = l & 3;
        int col = 8 * t + gg;
        float w0 = W[(8 * k + tt) * 64 + col];
        float w1 = W[(8 * k + tt + 4) * 64 + col];
        uint32_t h0 = f2tf(w0), h1 = f2tf(w1);
        uint32_t l0 = f2tf(w0 - __uint_as_float(h0));
        uint32_t l1 = f2tf(w1 - __uint_as_float(h1));
        reinterpret_cast<uint4*>(Wf)[i] = make_uint4(h0, h1, l0, l1);
    }
    __syncthreads();

    float* A = Ab + warp * 16 * 68;
    const int r0 = rb + warp * 16;

    #pragma unroll
    for (int p = 0; p < 8; p++) {
        int idx = p * 32 + lane;
        int r = idx >> 4, q = idx & 15;
        int row = r0 + r;
        float4 v = make_float4(0.f, 0.f, 0.f, 0.f);
        if (row < M) v = *reinterpret_cast<const float4*>(&X[(size_t)row * 64 + 4 * q]);
        *reinterpret_cast<float4*>(&A[r * 68 + 4 * q]) = v;
    }
    __syncwarp();

    float acc[8][4];
    #pragma unroll
    for (int t = 0; t < 8; t++) { acc[t][0] = acc[t][1] = acc[t][2] = acc[t][3] = 0.f; }

    #pragma unroll
    for (int k = 0; k < 8; k++) {
        const int c0 = 8 * k + tg;
        float a0 = A[g * 68 + c0],     a1 = A[(g + 8) * 68 + c0];
        float a2 = A[g * 68 + c0 + 4], a3 = A[(g + 8) * 68 + c0 + 4];
        uint32_t h0 = f2tf(a0), h1 = f2tf(a1), h2 = f2tf(a2), h3 = f2tf(a3);
        uint32_t o0 = f2tf(a0 - __uint_as_float(h0));
        uint32_t o1 = f2tf(a1 - __uint_as_float(h1));
        uint32_t o2 = f2tf(a2 - __uint_as_float(h2));
        uint32_t o3 = f2tf(a3 - __uint_as_float(h3));
        #pragma unroll
        for (int t = 0; t < 8; t++) {
            uint4 bb = reinterpret_cast<const uint4*>(Wf)[(k * 8 + t) * 32 + lane];
            mma8(acc[t][0], acc[t][1], acc[t][2], acc[t][3], h0, h1, h2, h3, bb.x, bb.y);
            mma8(acc[t][0], acc[t][1], acc[t][2], acc[t][3], o0, o1, o2, o3, bb.x, bb.y);
            mma8(acc[t][0], acc[t][1], acc[t][2], acc[t][3], h0, h1, h2, h3, bb.z, bb.w);
        }
    }

    const int row0 = r0 + g, row1 = r0 + g + 8;
    #pragma unroll
    for (int t = 0; t < 8; t++) {
        float2 bv = *reinterpret_cast<const float2*>(&bias[8 * t + 2 * tg]);
        int col = 8 * t + 2 * tg;
        if (row0 < M) *reinterpret_cast<float2*>(&Y[(size_t)row0 * 64 + col]) =
            make_float2(acc[t][0] + bv.x, acc[t][1] + bv.y);
        if (row1 < M) *reinterpret_cast<float2*>(&Y[(size_t)row1 * 64 + col]) =
            make_float2(acc[t][2] + bv.x, acc[t][3] + bv.y);
    }
}

// ---------------------------------------------------------------------------
// Fused CF output kernel (fp32-accurate split-tf32, two layers):
//   out = ssp(X @ Wc + bc) @ Wo + bo
// Same warp-independent structure as the edge kernel, no gather/scatter.
// ---------------------------------------------------------------------------
__global__ __launch_bounds__(256, 2)
void cfout_kernel(const float* __restrict__ X,
                  const float* __restrict__ Wc, const float* __restrict__ bc,
                  const float* __restrict__ Wo, const float* __restrict__ bo,
                  float* __restrict__ out, int M)
{
    extern __shared__ uint32_t SM[];
    uint32_t* WfA = SM;                        // 8192 u32 (uint4 tuples, Wc)
    uint32_t* WfB = SM + 8192;                 // 8192 u32 (Wo)
    float*    Ab  = (float*)(SM + 16384);

    const int tid = threadIdx.x, lane = tid & 31, warp = tid >> 5;
    const int g = lane >> 2, tg = lane & 3;

    #pragma unroll
    for (int p = 0; p < 8; p++) {
        int i = tid + 256 * p;
        int l = i & 31, t = (i >> 5) & 7, k = i >> 8;
        int gg = l >> 2, tt = l & 3;
        int col = 8 * t + gg;
        {
            float w0 = Wc[(8 * k + tt) * 64 + col];
            float w1 = Wc[(8 * k + tt + 4) * 64 + col];
            uint32_t h0 = f2tf(w0), h1 = f2tf(w1);
            uint32_t l0 = f2tf(w0 - __uint_as_float(h0));
            uint32_t l1 = f2tf(w1 - __uint_as_float(h1));
            reinterpret_cast<uint4*>(WfA)[i] = make_uint4(h0, h1, l0, l1);
        }
        {
            float w0 = Wo[(8 * k + tt) * 64 + col];
            float w1 = Wo[(8 * k + tt + 4) * 64 + col];
            uint32_t h0 = f2tf(w0), h1 = f2tf(w1);
            uint32_t l0 = f2tf(w0 - __uint_as_float(h0));
            uint32_t l1 = f2tf(w1 - __uint_as_float(h1));
            reinterpret_cast<uint4*>(WfB)[i] = make_uint4(h0, h1, l0, l1);
        }
    }
    __syncthreads();

    float* A = Ab + warp * 16 * 68;
    const int r0 = blockIdx.x * 128 + warp * 16;

    #pragma unroll
    for (int p = 0; p < 8; p++) {
        int idx = p * 32 + lane;
        int r = idx >> 4, q = idx & 15;
        int row = r0 + r;
        float4 v = make_float4(0.f, 0.f, 0.f, 0.f);
        if (row < M) v = *reinterpret_cast<const float4*>(&X[(size_t)row * 64 + 4 * q]);
        *reinterpret_cast<float4*>(&A[r * 68 + 4 * q]) = v;
    }
    __syncwarp();

    float acc[8][4];

    #pragma unroll
    for (int L = 0; L < 2; L++) {
        const uint32_t* Wf = (L == 0) ? WfA : WfB;
        #pragma unroll
        for (int t = 0; t < 8; t++) { acc[t][0] = acc[t][1] = acc[t][2] = acc[t][3] = 0.f; }
        #pragma unroll
        for (int k = 0; k < 8; k++) {
            const int c0 = 8 * k + tg;
            float a0 = A[g * 68 + c0],     a1 = A[(g + 8) * 68 + c0];
            float a2 = A[g * 68 + c0 + 4], a3 = A[(g + 8) * 68 + c0 + 4];
            uint32_t h0 = f2tf(a0), h1 = f2tf(a1), h2 = f2tf(a2), h3 = f2tf(a3);
            uint32_t o0 = f2tf(a0 - __uint_as_float(h0));
            uint32_t o1 = f2tf(a1 - __uint_as_float(h1));
            uint32_t o2 = f2tf(a2 - __uint_as_float(h2));
            uint32_t o3 = f2tf(a3 - __uint_as_float(h3));
            #pragma unroll
            for (int t = 0; t < 8; t++) {
                uint4 bb = reinterpret_cast<const uint4*>(Wf)[(k * 8 + t) * 32 + lane];
                mma8(acc[t][0], acc[t][1], acc[t][2], acc[t][3], h0, h1, h2, h3, bb.x, bb.y);
                mma8(acc[t][0], acc[t][1], acc[t][2], acc[t][3], o0, o1, o2, o3, bb.x, bb.y);
                mma8(acc[t][0], acc[t][1], acc[t][2], acc[t][3], h0, h1, h2, h3, bb.z, bb.w);
            }
        }
        __syncwarp();
        if (L == 0) {
            // C1 = ssp(acc + bc) -> A
            #pragma unroll
            for (int t = 0; t < 8; t++) {
                float2 bv = *reinterpret_cast<const float2*>(&bc[8 * t + 2 * tg]);
                int col = 8 * t + 2 * tg;
                *reinterpret_cast<float2*>(&A[g * 68 + col]) =
                    make_float2(sspf(acc[t][0] + bv.x), sspf(acc[t][1] + bv.y));
                *reinterpret_cast<float2*>(&A[(g + 8) * 68 + col]) =
                    make_float2(sspf(acc[t][2] + bv.x), sspf(acc[t][3] + bv.y));
            }
            __syncwarp();
        } else {
            const int row0 = r0 + g, row1 = r0 + g + 8;
            #pragma unroll
            for (int t = 0; t < 8; t++) {
                float2 bv = *reinterpret_cast<const float2*>(&bo[8 * t + 2 * tg]);
                int col = 8 * t + 2 * tg;
                if (row0 < M) *reinterpret_cast<float2*>(&out[(size_t)row0 * 64 + col]) =
                    make_float2(acc[t][0] + bv.x, acc[t][1] + bv.y);
                if (row1 < M) *reinterpret_cast<float2*>(&out[(size_t)row1 * 64 + col]) =
                    make_float2(acc[t][2] + bv.x, acc[t][3] + bv.y);
            }
        }
    }
}

// ---------------------------------------------------------------------------
// Fused edge kernel, 32 edges/warp (two 16-row subtiles sharing B-fragments):
//   f = ssp(ssp(EF@W1+b1)@W2+b2); agg[dst] += h[src]*f  (red.global.add.v4)
// ---------------------------------------------------------------------------
__global__ __launch_bounds__(256, 2)
void edge_kernel(const float* __restrict__ EF, const int* __restrict__ src,
                 const int* __restrict__ dst,
                 const float* __restrict__ W1, const float* __restrict__ b1,
                 const float* __restrict__ W2, const float* __restrict__ b2,
                 int E)
{
    extern __shared__ uint32_t SM[];
    uint32_t* Wf1 = SM;                        // 4096 u32
    uint32_t* Wf2 = SM + 4096;                 // 4096 u32
    float*    Ab  = (float*)(SM + 8192);       // 8 warps * 32 rows * 68

    const int tid = threadIdx.x, lane = tid & 31, warp = tid >> 5;
    const int g = lane >> 2, tg = lane & 3;

    #pragma unroll
    for (int p = 0; p < 8; p++) {
        int i = tid + 256 * p;                 // 0..2047
        int l = i & 31, t = (i >> 5) & 7, k = i >> 8;
        int gg = l >> 2, tt = l & 3;
        int col = 8 * t + gg;
        Wf1[2 * i]     = f2tf(W1[(8 * k + tt) * 64 + col]);
        Wf1[2 * i + 1] = f2tf(W1[(8 * k + tt + 4) * 64 + col]);
        Wf2[2 * i]     = f2tf(W2[(8 * k + tt) * 64 + col]);
        Wf2[2 * i + 1] = f2tf(W2[(8 * k + tt + 4) * 64 + col]);
    }
    __syncthreads();

    float* A = Ab + warp * 32 * 68;
    const int e0 = blockIdx.x * 256 + warp * 32;

    // Stage 32 edge-feature rows (coalesced f4)
    #pragma unroll
    for (int p = 0; p < 16; p++) {
        int idx = p * 32 + lane;               // 32 rows * 16 f4
        int r = idx >> 4, q = idx & 15;
        int e = e0 + r;
        float4 v = make_float4(0.f, 0.f, 0.f, 0.f);
        if (e < E) v = *reinterpret_cast<const float4*>(&EF[(size_t)e * 64 + 4 * q]);
        *reinterpret_cast<float4*>(&A[r * 68 + 4 * q]) = v;
    }
    __syncwarp();

    float acc[2][8][4];

    #pragma unroll
    for (int L = 0; L < 2; L++) {
        const uint32_t* Wf = (L == 0) ? Wf1 : Wf2;
        #pragma unroll
        for (int s = 0; s < 2; s++)
            #pragma unroll
            for (int t = 0; t < 8; t++)
                acc[s][t][0] = acc[s][t][1] = acc[s][t][2] = acc[s][t][3] = 0.f;

        #pragma unroll
        for (int k = 0; k < 8; k++) {
            const int c0 = 8 * k + tg;
            uint32_t u[2][4];
            #pragma unroll
            for (int s = 0; s < 2; s++) {
                const int R = s * 16;
                u[s][0] = f2tf(A[(R + g) * 68 + c0]);
                u[s][1] = f2tf(A[(R + g + 8) * 68 + c0]);
                u[s][2] = f2tf(A[(R + g) * 68 + c0 + 4]);
                u[s][3] = f2tf(A[(R + g + 8) * 68 + c0 + 4]);
            }
            #pragma unroll
            for (int t = 0; t < 8; t++) {
                uint2 bb = *reinterpret_cast<const uint2*>(&Wf[((k * 8 + t) * 32 + lane) * 2]);
                mma8(acc[0][t][0], acc[0][t][1], acc[0][t][2], acc[0][t][3],
                     u[0][0], u[0][1], u[0][2], u[0][3], bb.x, bb.y);
                mma8(acc[1][t][0], acc[1][t][1], acc[1][t][2], acc[1][t][3],
                     u[1][0], u[1][1], u[1][2], u[1][3], bb.x, bb.y);
            }
        }
        __syncwarp();   // all reads of A done before overwrite

        // Write ssp(acc + bias) back into A (C1 after L0, f after L1)
        const float* bias = (L == 0) ? b1 : b2;
        #pragma unroll
        for (int s = 0; s < 2; s++) {
            const int R = s * 16;
            #pragma unroll
            for (int t = 0; t < 8; t++) {
                float2 bv = *reinterpret_cast<const float2*>(&bias[8 * t + 2 * tg]);
                int col = 8 * t + 2 * tg;
                *reinterpret_cast<float2*>(&A[(R + g) * 68 + col]) =
                    make_float2(sspf(acc[s][t][0] + bv.x), sspf(acc[s][t][1] + bv.y));
                *reinterpret_cast<float2*>(&A[(R + g + 8) * 68 + col]) =
                    make_float2(sspf(acc[s][t][2] + bv.x), sspf(acc[s][t][3] + bv.y));
            }
        }
        __syncwarp();
    }

    // Epilogue: 2 lanes per edge; gather h[src] f4, multiply, red.v4 to agg[dst]
    {
        const int half = lane & 1;
        #pragma unroll
        for (int s = 0; s < 2; s++) {
            const int r = s * 16 + (lane >> 1);
            const int e = e0 + r;
            if (e < E) {
                const int sN = src[e], dN = dst[e];
                const float4* hp = reinterpret_cast<const float4*>(&g_h[(size_t)sN * 64]);
                float*        ap = &g_agg[(size_t)dN * 64];
                #pragma unroll
                for (int j = 0; j < 8; j++) {
                    int f4i = half + 2 * j;
                    float4 f  = *reinterpret_cast<const float4*>(&A[r * 68 + 4 * f4i]);
                    float4 h4 = __ldg(&hp[f4i]);
                    float m0 = f.x * h4.x, m1 = f.y * h4.y, m2 = f.z * h4.z, m3 = f.w * h4.w;
                    asm volatile("red.global.add.v4.f32 [%0], {%1, %2, %3, %4};"
                                 :: "l"(ap + 4 * f4i), "f"(m0), "f"(m1), "f"(m2), "f"(m3)
                                 : "memory");
                }
            }
        }
    }
}

// ---------------------------------------------------------------------------
// Launch sequence (one stream, graph-capturable, no allocs/syncs)
// ---------------------------------------------------------------------------
extern "C" void kernel_launch(void* const* d_in, const int* in_sizes, int n_in,
                              void* d_out, int out_size)
{
    const float* node = (const float*)d_in[0];
    const float* edge = (const float*)d_in[1];
    const int*   src  = (const int*)d_in[2];
    const int*   dst  = (const int*)d_in[3];
    const float* We1  = (const float*)d_in[4];
    const float* be1  = (const float*)d_in[5];
    const float* We2  = (const float*)d_in[6];
    const float* be2  = (const float*)d_in[7];
    const float* Wn   = (const float*)d_in[8];
    const float* bn   = (const float*)d_in[9];
    const float* Wc   = (const float*)d_in[10];
    const float* bc   = (const float*)d_in[11];
    const float* Wo   = (const float*)d_in[12];
    const float* bo   = (const float*)d_in[13];
    float* out = (float*)d_out;

    const int E  = in_sizes[2];
    const int Vn = in_sizes[0] / 64;

    float *h_ptr = nullptr, *agg_ptr = nullptr;
    cudaGetSymbolAddress((void**)&h_ptr, g_h);
    cudaGetSymbolAddress((void**)&agg_ptr, g_agg);

    cudaFuncSetAttribute(sgemm64_kernel<true>,
                         cudaFuncAttributeMaxDynamicSharedMemorySize, SMEM_GEMM);
    cudaFuncSetAttribute(edge_kernel,
                         cudaFuncAttributeMaxDynamicSharedMemorySize, SMEM_EDGE);
    cudaFuncSetAttribute(cfout_kernel,
                         cudaFuncAttributeMaxDynamicSharedMemorySize, SMEM_CF);

    const int nbV = (Vn + 127) / 128;
    const int nbE = (E + 255) / 256;

    // h = node @ Wn + bn ; zero agg   (split-tf32, fp32-accurate)
    sgemm64_kernel<true><<<nbV, 256, SMEM_GEMM>>>(node, Wn, bn, h_ptr, Vn);
    // fused CFConv edge pass: agg += h[src] * ssp(ssp(edge@W1+b1)@W2+b2)
    edge_kernel<<<nbE, 256, SMEM_EDGE>>>(edge, src, dst, We1, be1, We2, be2, E);
    // out = ssp(agg @ Wc + bc) @ Wo + bo   (fused two-layer, fp32-accurate)
    cfout_kernel<<<nbV, 256, SMEM_CF>>>(agg_ptr, Wc, bc, Wo, bo, out, Vn);
}